// round 2
// baseline (speedup 1.0000x reference)
#include <cuda_runtime.h>
#include <cstdint>

#define HID   256
#define TPIX  64          // pixels per CTA
#define NPAIR 32          // pixel pairs per CTA
#define HS2   516         // floats per pair-row in smem (258 float2 slots; 258 % 16 == 2 for bank spread)
#define KC    16          // k rows per weight chunk
#define NCHUNK 16         // 256 / 16

typedef unsigned long long ull;

// ---- packed fp32x2 helpers (sm_103a) ----
__device__ __forceinline__ ull dup2(float w) {
    ull r; asm("mov.b64 %0, {%1, %1};" : "=l"(r) : "f"(w)); return r;
}
__device__ __forceinline__ ull fma2(ull a, ull b, ull c) {
    ull d; asm("fma.rn.f32x2 %0, %1, %2, %3;" : "=l"(d) : "l"(a), "l"(b), "l"(c)); return d;
}
__device__ __forceinline__ float2 unpk(ull v) {
    float2 r; asm("mov.b64 {%0, %1}, %2;" : "=f"(r.x), "=f"(r.y) : "l"(v)); return r;
}
__device__ __forceinline__ float gelu_f(float x) {
    return 0.5f * x * (1.0f + erff(x * 0.70710678118654752f));
}

// per-image style constant: c_b[j] = b0[j] + emb[style_b] . W0[3:67, j]
__device__ float g_cstyle[16 * HID];

__global__ void style_pre(const int* __restrict__ sidx, const float* __restrict__ emb,
                          const float* __restrict__ W0, const float* __restrict__ b0) {
    int b = blockIdx.x, j = threadIdx.x;
    int s = sidx[b];
    float acc = b0[j];
#pragma unroll 8
    for (int k = 0; k < 64; k++)
        acc = fmaf(emb[s * 64 + k], W0[(3 + k) * HID + j], acc);
    g_cstyle[b * HID + j] = acc;
}

// One hidden layer: h <- gelu(h @ W + b), all in shared memory.
// Thread tiling: pg = tid&7 owns pixel-pairs pg*4..pg*4+3 (8 pixels),
//                ng = tid>>3 owns neurons ng*8..ng*8+7.
__device__ __forceinline__ void layer_pass(const float* __restrict__ Wg, const float* __restrict__ bg,
                                           float* hp, float* wt, int pg, int j0, int tid) {
    // prefetch weight chunk 0 (16 rows x 256 cols) into buffer 0
    const float4* src = (const float4*)Wg;
    float4 pf0 = src[tid], pf1 = src[tid + 256], pf2 = src[tid + 512], pf3 = src[tid + 768];
    {
        float4* dst = (float4*)wt;
        dst[tid] = pf0; dst[tid + 256] = pf1; dst[tid + 512] = pf2; dst[tid + 768] = pf3;
    }

    ull acc[4][8];
#pragma unroll
    for (int n = 0; n < 8; n++) {
        ull bd = dup2(bg[j0 + n]);
#pragma unroll
        for (int i = 0; i < 4; i++) acc[i][n] = bd;
    }
    __syncthreads();

    for (int ch = 0; ch < NCHUNK; ch++) {
        const float* wcur = wt + (ch & 1) * (KC * HID);
        if (ch + 1 < NCHUNK) {
            const float4* s2 = (const float4*)(Wg + (ch + 1) * KC * HID);
            pf0 = s2[tid]; pf1 = s2[tid + 256]; pf2 = s2[tid + 512]; pf3 = s2[tid + 768];
        }
        const int kbase = ch * KC;
#pragma unroll
        for (int kk = 0; kk < KC; kk += 2) {
            // packed h for 4 pixel-pairs, k and k+1  (16B-aligned: 516*4=2064 and 8*k are /16)
            ulonglong2 hv0 = *(const ulonglong2*)&hp[(pg * 4 + 0) * HS2 + 2 * (kbase + kk)];
            ulonglong2 hv1 = *(const ulonglong2*)&hp[(pg * 4 + 1) * HS2 + 2 * (kbase + kk)];
            ulonglong2 hv2 = *(const ulonglong2*)&hp[(pg * 4 + 2) * HS2 + 2 * (kbase + kk)];
            ulonglong2 hv3 = *(const ulonglong2*)&hp[(pg * 4 + 3) * HS2 + 2 * (kbase + kk)];
            {
                float4 wa = *(const float4*)&wcur[kk * HID + j0];
                float4 wb = *(const float4*)&wcur[kk * HID + j0 + 4];
                ull w[8] = {dup2(wa.x), dup2(wa.y), dup2(wa.z), dup2(wa.w),
                            dup2(wb.x), dup2(wb.y), dup2(wb.z), dup2(wb.w)};
#pragma unroll
                for (int n = 0; n < 8; n++) {
                    acc[0][n] = fma2(hv0.x, w[n], acc[0][n]);
                    acc[1][n] = fma2(hv1.x, w[n], acc[1][n]);
                    acc[2][n] = fma2(hv2.x, w[n], acc[2][n]);
                    acc[3][n] = fma2(hv3.x, w[n], acc[3][n]);
                }
            }
            {
                float4 wa = *(const float4*)&wcur[(kk + 1) * HID + j0];
                float4 wb = *(const float4*)&wcur[(kk + 1) * HID + j0 + 4];
                ull w[8] = {dup2(wa.x), dup2(wa.y), dup2(wa.z), dup2(wa.w),
                            dup2(wb.x), dup2(wb.y), dup2(wb.z), dup2(wb.w)};
#pragma unroll
                for (int n = 0; n < 8; n++) {
                    acc[0][n] = fma2(hv0.y, w[n], acc[0][n]);
                    acc[1][n] = fma2(hv1.y, w[n], acc[1][n]);
                    acc[2][n] = fma2(hv2.y, w[n], acc[2][n]);
                    acc[3][n] = fma2(hv3.y, w[n], acc[3][n]);
                }
            }
        }
        if (ch + 1 < NCHUNK) {
            float4* d2 = (float4*)(wt + ((ch + 1) & 1) * (KC * HID));
            d2[tid] = pf0; d2[tid + 256] = pf1; d2[tid + 512] = pf2; d2[tid + 768] = pf3;
        }
        __syncthreads();   // chunk ready for next iter; after last iter: all h reads done
    }

    // epilogue: gelu + write back into h (safe: everyone passed the last barrier)
#pragma unroll
    for (int i = 0; i < 4; i++) {
        int pr = pg * 4 + i;
#pragma unroll
        for (int n = 0; n < 8; n++) {
            float2 v = unpk(acc[i][n]);
            float2 st; st.x = gelu_f(v.x); st.y = gelu_f(v.y);
            *(float2*)&hp[pr * HS2 + 2 * (j0 + n)] = st;
        }
    }
    __syncthreads();
}

__global__ void __launch_bounds__(256, 2) nilut_main(
    const float* __restrict__ rgb,
    const float* __restrict__ W0,
    const float* __restrict__ W1, const float* __restrict__ b1,
    const float* __restrict__ W2, const float* __restrict__ b2,
    const float* __restrict__ W3, const float* __restrict__ b3,
    float* __restrict__ out, int HW) {
    extern __shared__ float sm[];
    float* hp   = sm;                       // NPAIR * HS2
    float* wt   = hp + NPAIR * HS2;         // 2 * KC * HID
    float* w0s  = wt + 2 * KC * HID;        // 3 * HID  (W0 rows 0..2)
    float* cvec = w0s + 3 * HID;            // HID
    float* w3s  = cvec + HID;               // 3 * HID  (transposed: [c][k])
    float* b3s  = w3s + 3 * HID;            // 4
    float* rgbs = b3s + 4;                  // 3 * TPIX

    const int tid = threadIdx.x;
    const int pg  = tid & 7;
    const int ng  = tid >> 3;
    const int j0  = ng * 8;

    const int pix0 = blockIdx.x * TPIX;
    const int b    = pix0 / HW;
    const int hw0  = pix0 - b * HW;

    // stage small tensors
    for (int i = tid; i < 3 * HID; i += 256) w0s[i] = W0[i];
    if (tid < HID) cvec[tid] = g_cstyle[b * HID + tid];
    for (int i = tid; i < 3 * HID; i += 256) { int k = i / 3, c = i - 3 * k; w3s[c * HID + k] = W3[i]; }
    if (tid < 3) b3s[tid] = b3[tid];
    for (int i = tid; i < 3 * TPIX; i += 256) {
        int c = i >> 6, p = i & 63;
        rgbs[c * TPIX + p] = rgb[(size_t)(b * 3 + c) * HW + hw0 + p];
    }
    __syncthreads();

    // ---- layer 0: h0 = gelu(rgb . W0[0:3] + c_b) ----
#pragma unroll
    for (int i = 0; i < 4; i++) {
        int pr = pg * 4 + i;
        int p0 = 2 * pr;
        float r0 = rgbs[p0],           r1 = rgbs[p0 + 1];
        float g0 = rgbs[TPIX + p0],    g1 = rgbs[TPIX + p0 + 1];
        float u0 = rgbs[2 * TPIX + p0], u1 = rgbs[2 * TPIX + p0 + 1];
#pragma unroll
        for (int n = 0; n < 8; n++) {
            int j = j0 + n;
            float base = cvec[j];
            float a0 = fmaf(r0, w0s[j], fmaf(g0, w0s[HID + j], fmaf(u0, w0s[2 * HID + j], base)));
            float a1 = fmaf(r1, w0s[j], fmaf(g1, w0s[HID + j], fmaf(u1, w0s[2 * HID + j], base)));
            float2 st; st.x = gelu_f(a0); st.y = gelu_f(a1);
            *(float2*)&hp[pr * HS2 + 2 * j] = st;
        }
    }
    __syncthreads();

    // ---- layers 1, 2 ----
    layer_pass(W1, b1, hp, wt, pg, j0, tid);
    layer_pass(W2, b2, hp, wt, pg, j0, tid);

    // ---- layer 3: out = sigmoid(h2 @ W3 + b3) ----
    if (tid < 3 * TPIX) {     // 192 threads: c = tid/64, p = tid%64 (warp-uniform c)
        int c = tid >> 6;
        int p = tid & 63;
        int pr = p >> 1, half = p & 1;
        const float* wr = &w3s[c * HID];
        float acc = b3s[c];
#pragma unroll 8
        for (int k = 0; k < HID; k++)
            acc = fmaf(hp[pr * HS2 + 2 * k + half], wr[k], acc);
        float o = 1.0f / (1.0f + expf(-acc));
        out[(size_t)(b * 3 + c) * HW + hw0 + p] = o;
    }
}

extern "C" void kernel_launch(void* const* d_in, const int* in_sizes, int n_in,
                              void* d_out, int out_size) {
    const float* rgb  = (const float*)d_in[0];
    const int*   sidx = (const int*)  d_in[1];
    const float* emb  = (const float*)d_in[2];
    const float* W0   = (const float*)d_in[3];
    const float* b0   = (const float*)d_in[4];
    const float* W1   = (const float*)d_in[5];
    const float* b1   = (const float*)d_in[6];
    const float* W2   = (const float*)d_in[7];
    const float* b2   = (const float*)d_in[8];
    const float* W3   = (const float*)d_in[9];
    const float* b3   = (const float*)d_in[10];
    float* out = (float*)d_out;

    int B  = in_sizes[1];                 // number of images (style_idx count)
    int HW = in_sizes[0] / (3 * B);       // pixels per image
    int N  = B * HW;

    style_pre<<<B, HID>>>(sidx, emb, W0, b0);

    int smem = (NPAIR * HS2 + 2 * KC * HID + 3 * HID + HID + 3 * HID + 4 + 3 * TPIX) * (int)sizeof(float);
    cudaFuncSetAttribute(nilut_main, cudaFuncAttributeMaxDynamicSharedMemorySize, smem);
    nilut_main<<<N / TPIX, 256, smem>>>(rgb, W0, W1, b1, W2, b2, W3, b3, out, HW);
}

// round 5
// speedup vs baseline: 2.5516x; 2.5516x over previous
#include <cuda_runtime.h>
#include <cuda_bf16.h>
#include <cstdint>

#define HID 256
#define MTILE 128

// ---- smem byte offsets ----
#define OFF_AHI 0                 // 128 rows * 528 B
#define AROWB   528
#define OFF_ALO 67584
#define OFF_WB  135168            // 2 buffers * 40960
#define WBUFSZ  40960             // (hi 256*80) + (lo 256*80)
#define WROWB   80
#define OFF_RED 135168            // overlays WB after last GEMM: 128*3*4 floats
#define OFF_OVL 176128            // overlays WB buf1 during prologue
#define OVL_W0  0                 // 768 f32
#define OVL_CV  3072              // 256 f32
#define OVL_RGB 4096              // 384 f32
#define OFF_B1  217088
#define OFF_B2  218112
#define OFF_W3  219136            // 256 * float4
#define OFF_B3  223232
#define SMEM_TOT 223360

// pre-split, pre-transposed weights:
// [layer2][chunk8][part2(hi/lo)][n256][k32] bf16, rows dense 64B
__device__ __align__(16) __nv_bfloat16 g_wb[262144];
__device__ float g_cstyle[16 * HID];

// ---------- helpers ----------
__device__ __forceinline__ uint32_t s2u(const void* p) {
    uint32_t a;
    asm("{ .reg .u64 t; cvta.to.shared.u64 t, %1; cvt.u32.u64 %0, t; }" : "=r"(a) : "l"(p));
    return a;
}
__device__ __forceinline__ void ldsm4(uint32_t* r, uint32_t addr) {
    asm volatile("ldmatrix.sync.aligned.m8n8.x4.shared.b16 {%0,%1,%2,%3}, [%4];"
                 : "=r"(r[0]), "=r"(r[1]), "=r"(r[2]), "=r"(r[3]) : "r"(addr));
}
__device__ __forceinline__ void mma16816(float* d, const uint32_t* a, uint32_t b0, uint32_t b1) {
    asm volatile("mma.sync.aligned.m16n8k16.row.col.f32.bf16.bf16.f32 "
                 "{%0,%1,%2,%3}, {%4,%5,%6,%7}, {%8,%9}, {%0,%1,%2,%3};"
                 : "+f"(d[0]), "+f"(d[1]), "+f"(d[2]), "+f"(d[3])
                 : "r"(a[0]), "r"(a[1]), "r"(a[2]), "r"(a[3]), "r"(b0), "r"(b1));
}
__device__ __forceinline__ void cpasync16(uint32_t dst, const void* src) {
    asm volatile("cp.async.cg.shared.global [%0], [%1], 16;" :: "r"(dst), "l"(src));
}
#define CP_COMMIT() asm volatile("cp.async.commit_group;" ::: "memory")
#define CP_WAIT(n)  asm volatile("cp.async.wait_group %0;" :: "n"(n) : "memory")

__device__ __forceinline__ float gelu_f(float x) {
    return 0.5f * x * (1.0f + erff(x * 0.70710678118654752f));
}
__device__ __forceinline__ void split2(float a0, float a1, uint32_t& hi, uint32_t& lo) {
    __nv_bfloat16 h0 = __float2bfloat16(a0), h1 = __float2bfloat16(a1);
    __nv_bfloat16 l0 = __float2bfloat16(a0 - __bfloat162float(h0));
    __nv_bfloat16 l1 = __float2bfloat16(a1 - __bfloat162float(h1));
    hi = ((uint32_t)__bfloat16_as_ushort(h1) << 16) | __bfloat16_as_ushort(h0);
    lo = ((uint32_t)__bfloat16_as_ushort(l1) << 16) | __bfloat16_as_ushort(l0);
}

// ---------- pre-kernels ----------
__global__ void style_pre(const int* __restrict__ sidx, const float* __restrict__ emb,
                          const float* __restrict__ W0, const float* __restrict__ b0) {
    int b = blockIdx.x, j = threadIdx.x;
    int s = sidx[b];
    float acc = b0[j];
#pragma unroll 8
    for (int k = 0; k < 64; k++)
        acc = fmaf(emb[s * 64 + k], W0[(3 + k) * HID + j], acc);
    g_cstyle[b * HID + j] = acc;
}

__global__ void prep_w(const float* __restrict__ W1, const float* __restrict__ W2) {
    int idx = blockIdx.x * 256 + threadIdx.x;     // 0..131071
    int l = idx >> 16;
    int k = (idx >> 8) & 255;
    int n = idx & 255;
    float w = (l ? W2 : W1)[k * HID + n];
    __nv_bfloat16 hi = __float2bfloat16(w);
    __nv_bfloat16 lo = __float2bfloat16(w - __bfloat162float(hi));
    int chunk = k >> 5, kc = k & 31;
    size_t base = (size_t)(l * 8 + chunk) * 16384 + (size_t)n * 32 + kc;
    g_wb[base] = hi;             // part 0
    g_wb[base + 8192] = lo;      // part 1
}

// ---------- main kernel ----------
__device__ __forceinline__ void prefetch_chunk(uint32_t wb, const __nv_bfloat16* gbase, int tid) {
    const char* g = (const char*)gbase;
#pragma unroll
    for (int i = 0; i < 8; i++) {
        int idx = tid + i * 256;          // 0..2047
        int part = idx >> 10;
        int rem = idx & 1023;
        int n = rem >> 2, cc = rem & 3;
        cpasync16(wb + part * 20480 + n * WROWB + cc * 16,
                  g + part * 16384 + n * 64 + cc * 16);
    }
}

struct WarpCtx {
    int mg, ng, M0, lane;
    int arow, ak16off;   // A ldmatrix lane geometry
    int brow, bk16off;   // B ldmatrix lane geometry
};

__device__ __forceinline__ void run_layer(char* sm, uint32_t sb, const __nv_bfloat16* gbase,
                                          const __nv_bfloat16* tail, const WarpCtx& W,
                                          float C[4][8][4], int tid) {
    for (int c = 0; c < 8; c++) {
        __syncthreads();
        const __nv_bfloat16* gn = (c < 7) ? gbase + (size_t)(c + 1) * 16384 : tail;
        if (gn) {
            prefetch_chunk(sb + OFF_WB + ((c + 1) & 1) * WBUFSZ, gn, tid);
            CP_COMMIT();
            CP_WAIT(1);
        } else {
            CP_WAIT(0);
        }
        __syncthreads();
        const uint32_t wb = sb + OFF_WB + (c & 1) * WBUFSZ;
#pragma unroll
        for (int kk = 0; kk < 32; kk += 16) {
            const int kglob = c * 32 + kk;
            uint32_t ah[4][4], al[4][4];
#pragma unroll
            for (int mt = 0; mt < 4; mt++) {
                uint32_t ao = sb + OFF_AHI + (uint32_t)(W.M0 + mt * 16 + W.arow) * AROWB
                              + (uint32_t)kglob * 2 + W.ak16off;
                ldsm4(ah[mt], ao);
                ldsm4(al[mt], ao + (OFF_ALO - OFF_AHI));
            }
#pragma unroll
            for (int ntp = 0; ntp < 4; ntp++) {
                uint32_t bo = wb + (uint32_t)(W.ng * 64 + ntp * 16 + W.brow) * WROWB
                              + (uint32_t)kk * 2 + W.bk16off;
                uint32_t bh[4], bl[4];
                ldsm4(bh, bo);
                ldsm4(bl, bo + 20480);
#pragma unroll
                for (int mt = 0; mt < 4; mt++) {
                    float* c0 = C[mt][2 * ntp];
                    float* c1 = C[mt][2 * ntp + 1];
                    mma16816(c0, ah[mt], bh[0], bh[1]);
                    mma16816(c0, ah[mt], bl[0], bl[1]);
                    mma16816(c0, al[mt], bh[0], bh[1]);
                    mma16816(c1, ah[mt], bh[2], bh[3]);
                    mma16816(c1, ah[mt], bl[2], bl[3]);
                    mma16816(c1, al[mt], bh[2], bh[3]);
                }
            }
        }
    }
    __syncthreads();   // all LDSM reads done before A / RED gets rewritten
}

__global__ void __launch_bounds__(256, 1) nilut_mma(
    const float* __restrict__ rgb, const float* __restrict__ W0,
    const float* __restrict__ b1, const float* __restrict__ b2,
    const float* __restrict__ W3, const float* __restrict__ b3,
    float* __restrict__ out, int HW)
{
    extern __shared__ __align__(1024) char sm[];
    const uint32_t sb = s2u(sm);
    const int tid = threadIdx.x, wid = tid >> 5, lane = tid & 31;

    WarpCtx W;
    W.lane = lane;
    W.mg = wid & 1; W.ng = wid >> 1; W.M0 = W.mg * 64;
    W.arow = lane & 15;              W.ak16off = ((lane >> 4) & 1) * 16;
    W.brow = (lane & 7) + ((lane >> 4) << 3);
    W.bk16off = ((lane >> 3) & 1) * 16;

    const int pix0 = blockIdx.x * MTILE;
    const int b = pix0 / HW, hw0 = pix0 - b * HW;

    // start weight chunk (layer0, chunk0) prefetch ASAP -> buf0
    prefetch_chunk(sb + OFF_WB, g_wb, tid);
    CP_COMMIT();

    // stage resident + overlay smalls
    float* b1s = (float*)(sm + OFF_B1);
    float* b2s = (float*)(sm + OFF_B2);
    float* w3p = (float*)(sm + OFF_W3);
    float* b3s = (float*)(sm + OFF_B3);
    float* w0s  = (float*)(sm + OFF_OVL + OVL_W0);
    float* cvec = (float*)(sm + OFF_OVL + OVL_CV);
    float* rgbs = (float*)(sm + OFF_OVL + OVL_RGB);

    b1s[tid] = b1[tid];
    b2s[tid] = b2[tid];
    {
        w3p[4 * tid + 0] = W3[3 * tid + 0];
        w3p[4 * tid + 1] = W3[3 * tid + 1];
        w3p[4 * tid + 2] = W3[3 * tid + 2];
        w3p[4 * tid + 3] = 0.f;
    }
    if (tid < 4) b3s[tid] = (tid < 3) ? b3[tid] : 0.f;
    for (int i = tid; i < 768; i += 256) w0s[i] = W0[i];
    cvec[tid] = g_cstyle[b * HID + tid];
    for (int i = tid; i < 384; i += 256) {
        int c = i >> 7, px = i & 127;
        rgbs[c * 128 + px] = rgb[(size_t)(b * 3 + c) * HW + hw0 + px];
    }
    __syncthreads();

    // ---- layer 0 prologue: A = split(gelu(rgb.W0[0:3] + cvec)) ----
    {
        int wq = wid & 3, half = wid >> 2;
        int p = wq * 32 + lane;
        float rr = rgbs[p], gg = rgbs[128 + p], uu = rgbs[256 + p];
        char* arow_hi = sm + OFF_AHI + p * AROWB;
        char* arow_lo = sm + OFF_ALO + p * AROWB;
#pragma unroll 4
        for (int q = 0; q < 64; q++) {
            int j = half * 128 + 2 * q;
            float2 w0a = *(const float2*)&w0s[j];
            float2 w0b = *(const float2*)&w0s[256 + j];
            float2 w0c = *(const float2*)&w0s[512 + j];
            float2 cv  = *(const float2*)&cvec[j];
            float a0 = fmaf(rr, w0a.x, fmaf(gg, w0b.x, fmaf(uu, w0c.x, cv.x)));
            float a1 = fmaf(rr, w0a.y, fmaf(gg, w0b.y, fmaf(uu, w0c.y, cv.y)));
            uint32_t hi, lo;
            split2(gelu_f(a0), gelu_f(a1), hi, lo);
            *(uint32_t*)(arow_hi + j * 2) = hi;
            *(uint32_t*)(arow_lo + j * 2) = lo;
        }
    }

    float C[4][8][4];
#pragma unroll
    for (int mt = 0; mt < 4; mt++)
#pragma unroll
        for (int nt = 0; nt < 8; nt++)
#pragma unroll
            for (int q = 0; q < 4; q++) C[mt][nt][q] = 0.f;

    // ---- layer 1 GEMM ----
    run_layer(sm, sb, g_wb, g_wb + (size_t)8 * 16384, W, C, tid);

    // ---- epilogue 1: C -> gelu -> A (hi/lo), zero C ----
    {
        const int r0b = W.M0 + (lane >> 2);
#pragma unroll
        for (int mt = 0; mt < 4; mt++) {
            int r0 = r0b + mt * 16, r1 = r0 + 8;
#pragma unroll
            for (int nt = 0; nt < 8; nt++) {
                int j0 = W.ng * 64 + nt * 8 + (lane & 3) * 2;
                float2 bj = *(const float2*)(sm + OFF_B1 + j0 * 4);
                float v0 = gelu_f(C[mt][nt][0] + bj.x);
                float v1 = gelu_f(C[mt][nt][1] + bj.y);
                float v2 = gelu_f(C[mt][nt][2] + bj.x);
                float v3 = gelu_f(C[mt][nt][3] + bj.y);
                uint32_t h01, l01, h23, l23;
                split2(v0, v1, h01, l01);
                split2(v2, v3, h23, l23);
                *(uint32_t*)(sm + OFF_AHI + r0 * AROWB + j0 * 2) = h01;
                *(uint32_t*)(sm + OFF_ALO + r0 * AROWB + j0 * 2) = l01;
                *(uint32_t*)(sm + OFF_AHI + r1 * AROWB + j0 * 2) = h23;
                *(uint32_t*)(sm + OFF_ALO + r1 * AROWB + j0 * 2) = l23;
                C[mt][nt][0] = 0.f; C[mt][nt][1] = 0.f;
                C[mt][nt][2] = 0.f; C[mt][nt][3] = 0.f;
            }
        }
    }
    __syncthreads();   // A ready for layer 2

    // ---- layer 2 GEMM (chunk0 already prefetched by layer-1 tail) ----
    run_layer(sm, sb, g_wb + (size_t)8 * 16384, nullptr, W, C, tid);

    // ---- head epilogue: gelu -> dot W3 -> reduce -> sigmoid ----
    {
        float* red = (float*)(sm + OFF_RED);   // [128][3][4]
        float acc[4][2][3];
#pragma unroll
        for (int mt = 0; mt < 4; mt++)
#pragma unroll
            for (int h = 0; h < 2; h++)
                acc[mt][h][0] = acc[mt][h][1] = acc[mt][h][2] = 0.f;

#pragma unroll
        for (int mt = 0; mt < 4; mt++) {
#pragma unroll
            for (int nt = 0; nt < 8; nt++) {
                int j0 = W.ng * 64 + nt * 8 + (lane & 3) * 2;
                float2 bj = *(const float2*)(sm + OFF_B2 + j0 * 4);
                float4 wa = *(const float4*)(sm + OFF_W3 + j0 * 16);
                float4 wbv = *(const float4*)(sm + OFF_W3 + (j0 + 1) * 16);
                float v0 = gelu_f(C[mt][nt][0] + bj.x);
                float v1 = gelu_f(C[mt][nt][1] + bj.y);
                float v2 = gelu_f(C[mt][nt][2] + bj.x);
                float v3 = gelu_f(C[mt][nt][3] + bj.y);
                acc[mt][0][0] = fmaf(v0, wa.x, fmaf(v1, wbv.x, acc[mt][0][0]));
                acc[mt][0][1] = fmaf(v0, wa.y, fmaf(v1, wbv.y, acc[mt][0][1]));
                acc[mt][0][2] = fmaf(v0, wa.z, fmaf(v1, wbv.z, acc[mt][0][2]));
                acc[mt][1][0] = fmaf(v2, wa.x, fmaf(v3, wbv.x, acc[mt][1][0]));
                acc[mt][1][1] = fmaf(v2, wa.y, fmaf(v3, wbv.y, acc[mt][1][1]));
                acc[mt][1][2] = fmaf(v2, wa.z, fmaf(v3, wbv.z, acc[mt][1][2]));
            }
        }
        // reduce across the 4 lanes sharing a row (lane & 3)
#pragma unroll
        for (int mt = 0; mt < 4; mt++)
#pragma unroll
            for (int h = 0; h < 2; h++)
#pragma unroll
                for (int ch = 0; ch < 3; ch++) {
                    float v = acc[mt][h][ch];
                    v += __shfl_xor_sync(0xffffffffu, v, 1);
                    v += __shfl_xor_sync(0xffffffffu, v, 2);
                    acc[mt][h][ch] = v;
                }
        if ((lane & 3) == 0) {
#pragma unroll
            for (int mt = 0; mt < 4; mt++)
#pragma unroll
                for (int h = 0; h < 2; h++) {
                    int r = W.M0 + mt * 16 + (lane >> 2) + h * 8;
#pragma unroll
                    for (int ch = 0; ch < 3; ch++)
                        red[(r * 3 + ch) * 4 + W.ng] = acc[mt][h][ch];
                }
        }
        __syncthreads();
        for (int i = tid; i < 384; i += 256) {
            int ch = i >> 7, row = i & 127;
            const float* rr = &red[(row * 3 + ch) * 4];
            float s = rr[0] + rr[1] + rr[2] + rr[3] + b3s[ch];
            out[(size_t)(b * 3 + ch) * HW + hw0 + row] = 1.f / (1.f + expf(-s));
        }
    }
}

extern "C" void kernel_launch(void* const* d_in, const int* in_sizes, int n_in,
                              void* d_out, int out_size) {
    const float* rgb  = (const float*)d_in[0];
    const int*   sidx = (const int*)  d_in[1];
    const float* emb  = (const float*)d_in[2];
    const float* W0   = (const float*)d_in[3];
    const float* b0   = (const float*)d_in[4];
    const float* W1   = (const float*)d_in[5];
    const float* b1   = (const float*)d_in[6];
    const float* W2   = (const float*)d_in[7];
    const float* b2   = (const float*)d_in[8];
    const float* W3   = (const float*)d_in[9];
    const float* b3   = (const float*)d_in[10];
    float* out = (float*)d_out;

    int B  = in_sizes[1];
    int HW = in_sizes[0] / (3 * B);
    int N  = B * HW;

    style_pre<<<B, HID>>>(sidx, emb, W0, b0);
    prep_w<<<512, 256>>>(W1, W2);

    cudaFuncSetAttribute(nilut_mma, cudaFuncAttributeMaxDynamicSharedMemorySize, SMEM_TOT);
    nilut_mma<<<N / MTILE, 256, SMEM_TOT>>>(rgb, W0, b1, b2, W3, b3, out, HW);
}

// round 6
// speedup vs baseline: 4.4346x; 1.7380x over previous
#include <cuda_runtime.h>
#include <cuda_fp16.h>
#include <cstdint>

#define HID 256
#define MTILE 128

// ---- smem byte offsets ----
#define OFF_A   0                 // 128 rows * 528 B (fp16 activations)
#define AROWB   528
#define OFF_WB  67584             // 2 buffers * 36864
#define WBUFSZ  36864             // 256 rows * 144 B (k=64 fp16 + 16B pad)
#define WROWB   144
#define OFF_RED 67584             // overlays WB after last GEMM: 128*3*4 floats
#define OFF_OVL 104448            // overlays WB buf1 during prologue
#define OVL_W0  0                 // 768 f32
#define OVL_CV  3072              // 256 f32
#define OVL_RGB 4096              // 384 f32
#define OFF_B1  141312
#define OFF_B2  142336
#define OFF_W3  143360            // [3][256] f32
#define OFF_B3  146432
#define SMEM_TOT 146448

// fp16 weights, transposed: [layer2][chunk4][n256][k64]
__device__ __align__(16) __half g_wb[131072];
__device__ float g_cstyle[16 * HID];

// ---------- helpers ----------
__device__ __forceinline__ uint32_t s2u(const void* p) {
    uint32_t a;
    asm("{ .reg .u64 t; cvta.to.shared.u64 t, %1; cvt.u32.u64 %0, t; }" : "=r"(a) : "l"(p));
    return a;
}
__device__ __forceinline__ void ldsm4(uint32_t* r, uint32_t addr) {
    asm volatile("ldmatrix.sync.aligned.m8n8.x4.shared.b16 {%0,%1,%2,%3}, [%4];"
                 : "=r"(r[0]), "=r"(r[1]), "=r"(r[2]), "=r"(r[3]) : "r"(addr));
}
__device__ __forceinline__ void mma16816(float* d, const uint32_t* a, uint32_t b0, uint32_t b1) {
    asm volatile("mma.sync.aligned.m16n8k16.row.col.f32.f16.f16.f32 "
                 "{%0,%1,%2,%3}, {%4,%5,%6,%7}, {%8,%9}, {%0,%1,%2,%3};"
                 : "+f"(d[0]), "+f"(d[1]), "+f"(d[2]), "+f"(d[3])
                 : "r"(a[0]), "r"(a[1]), "r"(a[2]), "r"(a[3]), "r"(b0), "r"(b1));
}
__device__ __forceinline__ void cpasync16(uint32_t dst, const void* src) {
    asm volatile("cp.async.cg.shared.global [%0], [%1], 16;" :: "r"(dst), "l"(src));
}
#define CP_COMMIT() asm volatile("cp.async.commit_group;" ::: "memory")
#define CP_WAIT(n)  asm volatile("cp.async.wait_group %0;" :: "n"(n) : "memory")

__device__ __forceinline__ float gelu_f(float x) {
    return 0.5f * x * (1.0f + erff(x * 0.70710678118654752f));
}
__device__ __forceinline__ uint32_t pack_h2(float lo, float hi) {
    __half2 h = __floats2half2_rn(lo, hi);
    return *(uint32_t*)&h;
}

// ---------- pre-kernels ----------
__global__ void style_pre(const int* __restrict__ sidx, const float* __restrict__ emb,
                          const float* __restrict__ W0, const float* __restrict__ b0) {
    int b = blockIdx.x, j = threadIdx.x;
    int s = sidx[b];
    float acc = b0[j];
#pragma unroll 8
    for (int k = 0; k < 64; k++)
        acc = fmaf(emb[s * 64 + k], W0[(3 + k) * HID + j], acc);
    g_cstyle[b * HID + j] = acc;
}

__global__ void prep_w(const float* __restrict__ W1, const float* __restrict__ W2) {
    int idx = blockIdx.x * 256 + threadIdx.x;     // 0..131071
    int l = idx >> 16;
    int k = (idx >> 8) & 255;
    int n = idx & 255;
    float w = (l ? W2 : W1)[k * HID + n];         // W[k][n] -> B[n][k]
    int chunk = k >> 6, kc = k & 63;
    g_wb[((size_t)(l * 4 + chunk) * 256 + n) * 64 + kc] = __float2half_rn(w);
}

// ---------- main kernel ----------
__device__ __forceinline__ void prefetch_chunk(uint32_t wb, const __half* gbase, int tid) {
    const char* g = (const char*)gbase + tid * 128;   // row tid, 128B
    uint32_t d = wb + tid * WROWB;
#pragma unroll
    for (int c = 0; c < 8; c++)
        cpasync16(d + c * 16, g + c * 16);
}

struct WarpCtx {
    int mg, ng, M0, lane;
    int arow, ak16off;
    int brow, bk16off;
};

__device__ __forceinline__ void run_layer(char* sm, uint32_t sb, const __half* gbase,
                                          const __half* tail, const WarpCtx& W,
                                          float C[4][8][4], int tid) {
    for (int c = 0; c < 4; c++) {
        __syncthreads();
        const __half* gn = (c < 3) ? gbase + (size_t)(c + 1) * 16384 : tail;
        if (gn) {
            prefetch_chunk(sb + OFF_WB + ((c + 1) & 1) * WBUFSZ, gn, tid);
            CP_COMMIT();
            CP_WAIT(1);
        } else {
            CP_WAIT(0);
        }
        __syncthreads();
        const uint32_t wb = sb + OFF_WB + (c & 1) * WBUFSZ;
#pragma unroll
        for (int kk = 0; kk < 64; kk += 16) {
            const int kglob = c * 64 + kk;
            uint32_t ah[4][4];
#pragma unroll
            for (int mt = 0; mt < 4; mt++) {
                uint32_t ao = sb + OFF_A + (uint32_t)(W.M0 + mt * 16 + W.arow) * AROWB
                              + (uint32_t)kglob * 2 + W.ak16off;
                ldsm4(ah[mt], ao);
            }
#pragma unroll
            for (int ntp = 0; ntp < 4; ntp++) {
                uint32_t bo = wb + (uint32_t)(W.ng * 64 + ntp * 16 + W.brow) * WROWB
                              + (uint32_t)kk * 2 + W.bk16off;
                uint32_t bh[4];
                ldsm4(bh, bo);
#pragma unroll
                for (int mt = 0; mt < 4; mt++) {
                    mma16816(C[mt][2 * ntp],     ah[mt], bh[0], bh[1]);
                    mma16816(C[mt][2 * ntp + 1], ah[mt], bh[2], bh[3]);
                }
            }
        }
    }
    __syncthreads();   // all LDSM reads done before A / RED gets rewritten
}

__global__ void __launch_bounds__(256, 1) nilut_mma(
    const float* __restrict__ rgb, const float* __restrict__ W0,
    const float* __restrict__ b1, const float* __restrict__ b2,
    const float* __restrict__ W3, const float* __restrict__ b3,
    float* __restrict__ out, int HW)
{
    extern __shared__ __align__(1024) char sm[];
    const uint32_t sb = s2u(sm);
    const int tid = threadIdx.x, wid = tid >> 5, lane = tid & 31;

    WarpCtx W;
    W.lane = lane;
    W.mg = wid & 1; W.ng = wid >> 1; W.M0 = W.mg * 64;
    W.arow = lane & 15;              W.ak16off = ((lane >> 4) & 1) * 16;
    W.brow = (lane & 7) + ((lane >> 4) << 3);
    W.bk16off = ((lane >> 3) & 1) * 16;

    const int pix0 = blockIdx.x * MTILE;
    const int b = pix0 / HW, hw0 = pix0 - b * HW;

    // start weight chunk (layer1, chunk0) prefetch ASAP -> buf0
    prefetch_chunk(sb + OFF_WB, g_wb, tid);
    CP_COMMIT();

    // stage resident + overlay smalls
    float* b1s = (float*)(sm + OFF_B1);
    float* b2s = (float*)(sm + OFF_B2);
    float* w3s = (float*)(sm + OFF_W3);
    float* b3s = (float*)(sm + OFF_B3);
    float* w0s  = (float*)(sm + OFF_OVL + OVL_W0);
    float* cvec = (float*)(sm + OFF_OVL + OVL_CV);
    float* rgbs = (float*)(sm + OFF_OVL + OVL_RGB);

    b1s[tid] = b1[tid];
    b2s[tid] = b2[tid];
#pragma unroll
    for (int c = 0; c < 3; c++) w3s[c * 256 + tid] = W3[3 * tid + c];
    if (tid < 4) b3s[tid] = (tid < 3) ? b3[tid] : 0.f;
    for (int i = tid; i < 768; i += 256) w0s[i] = W0[i];
    cvec[tid] = g_cstyle[b * HID + tid];
    for (int i = tid; i < 384; i += 256) {
        int c = i >> 7, px = i & 127;
        rgbs[c * 128 + px] = rgb[(size_t)(b * 3 + c) * HW + hw0 + px];
    }
    __syncthreads();

    // ---- layer 0 prologue: A = fp16(gelu(rgb.W0[0:3] + cvec)) ----
    {
        int wq = wid & 3, half = wid >> 2;
        int p = wq * 32 + lane;
        float rr = rgbs[p], gg = rgbs[128 + p], uu = rgbs[256 + p];
        char* arow = sm + OFF_A + p * AROWB;
#pragma unroll 4
        for (int q = 0; q < 64; q++) {
            int j = half * 128 + 2 * q;
            float2 w0a = *(const float2*)&w0s[j];
            float2 w0b = *(const float2*)&w0s[256 + j];
            float2 w0c = *(const float2*)&w0s[512 + j];
            float2 cv  = *(const float2*)&cvec[j];
            float a0 = fmaf(rr, w0a.x, fmaf(gg, w0b.x, fmaf(uu, w0c.x, cv.x)));
            float a1 = fmaf(rr, w0a.y, fmaf(gg, w0b.y, fmaf(uu, w0c.y, cv.y)));
            *(uint32_t*)(arow + j * 2) = pack_h2(gelu_f(a0), gelu_f(a1));
        }
    }

    float C[4][8][4];
#pragma unroll
    for (int mt = 0; mt < 4; mt++)
#pragma unroll
        for (int nt = 0; nt < 8; nt++)
#pragma unroll
            for (int q = 0; q < 4; q++) C[mt][nt][q] = 0.f;

    // ---- layer 1 GEMM ----
    run_layer(sm, sb, g_wb, g_wb + (size_t)4 * 16384, W, C, tid);

    // ---- epilogue 1: C -> gelu -> A (fp16), zero C ----
    {
        const int r0b = W.M0 + (lane >> 2);
#pragma unroll
        for (int mt = 0; mt < 4; mt++) {
            int r0 = r0b + mt * 16, r1 = r0 + 8;
#pragma unroll
            for (int nt = 0; nt < 8; nt++) {
                int j0 = W.ng * 64 + nt * 8 + (lane & 3) * 2;
                float2 bj = *(const float2*)(sm + OFF_B1 + j0 * 4);
                float v0 = gelu_f(C[mt][nt][0] + bj.x);
                float v1 = gelu_f(C[mt][nt][1] + bj.y);
                float v2 = gelu_f(C[mt][nt][2] + bj.x);
                float v3 = gelu_f(C[mt][nt][3] + bj.y);
                *(uint32_t*)(sm + OFF_A + r0 * AROWB + j0 * 2) = pack_h2(v0, v1);
                *(uint32_t*)(sm + OFF_A + r1 * AROWB + j0 * 2) = pack_h2(v2, v3);
                C[mt][nt][0] = 0.f; C[mt][nt][1] = 0.f;
                C[mt][nt][2] = 0.f; C[mt][nt][3] = 0.f;
            }
        }
    }
    __syncthreads();   // A ready for layer 2

    // ---- layer 2 GEMM (chunk0 already prefetched by layer-1 tail) ----
    run_layer(sm, sb, g_wb + (size_t)4 * 16384, nullptr, W, C, tid);

    // ---- head epilogue: gelu -> dot W3 -> reduce -> sigmoid ----
    {
        float* red = (float*)(sm + OFF_RED);   // [128][3][4]
        float acc[4][2][3];
#pragma unroll
        for (int mt = 0; mt < 4; mt++)
#pragma unroll
            for (int h = 0; h < 2; h++)
                acc[mt][h][0] = acc[mt][h][1] = acc[mt][h][2] = 0.f;

#pragma unroll
        for (int mt = 0; mt < 4; mt++) {
#pragma unroll
            for (int nt = 0; nt < 8; nt++) {
                int j0 = W.ng * 64 + nt * 8 + (lane & 3) * 2;
                float2 bj = *(const float2*)(sm + OFF_B2 + j0 * 4);
                float2 wx = *(const float2*)(sm + OFF_W3 + j0 * 4);
                float2 wy = *(const float2*)(sm + OFF_W3 + 1024 + j0 * 4);
                float2 wz = *(const float2*)(sm + OFF_W3 + 2048 + j0 * 4);
                float v0 = gelu_f(C[mt][nt][0] + bj.x);
                float v1 = gelu_f(C[mt][nt][1] + bj.y);
                float v2 = gelu_f(C[mt][nt][2] + bj.x);
                float v3 = gelu_f(C[mt][nt][3] + bj.y);
                acc[mt][0][0] = fmaf(v0, wx.x, fmaf(v1, wx.y, acc[mt][0][0]));
                acc[mt][0][1] = fmaf(v0, wy.x, fmaf(v1, wy.y, acc[mt][0][1]));
                acc[mt][0][2] = fmaf(v0, wz.x, fmaf(v1, wz.y, acc[mt][0][2]));
                acc[mt][1][0] = fmaf(v2, wx.x, fmaf(v3, wx.y, acc[mt][1][0]));
                acc[mt][1][1] = fmaf(v2, wy.x, fmaf(v3, wy.y, acc[mt][1][1]));
                acc[mt][1][2] = fmaf(v2, wz.x, fmaf(v3, wz.y, acc[mt][1][2]));
            }
        }
#pragma unroll
        for (int mt = 0; mt < 4; mt++)
#pragma unroll
            for (int h = 0; h < 2; h++)
#pragma unroll
                for (int ch = 0; ch < 3; ch++) {
                    float v = acc[mt][h][ch];
                    v += __shfl_xor_sync(0xffffffffu, v, 1);
                    v += __shfl_xor_sync(0xffffffffu, v, 2);
                    acc[mt][h][ch] = v;
                }
        if ((lane & 3) == 0) {
#pragma unroll
            for (int mt = 0; mt < 4; mt++)
#pragma unroll
                for (int h = 0; h < 2; h++) {
                    int r = W.M0 + mt * 16 + (lane >> 2) + h * 8;
#pragma unroll
                    for (int ch = 0; ch < 3; ch++)
                        red[(r * 3 + ch) * 4 + W.ng] = acc[mt][h][ch];
                }
        }
        __syncthreads();
        for (int i = tid; i < 384; i += 256) {
            int ch = i >> 7, row = i & 127;
            const float* rr = &red[(row * 3 + ch) * 4];
            float s = rr[0] + rr[1] + rr[2] + rr[3] + b3s[ch];
            out[(size_t)(b * 3 + ch) * HW + hw0 + row] = 1.f / (1.f + expf(-s));
        }
    }
}

extern "C" void kernel_launch(void* const* d_in, const int* in_sizes, int n_in,
                              void* d_out, int out_size) {
    const float* rgb  = (const float*)d_in[0];
    const int*   sidx = (const int*)  d_in[1];
    const float* emb  = (const float*)d_in[2];
    const float* W0   = (const float*)d_in[3];
    const float* b0   = (const float*)d_in[4];
    const float* W1   = (const float*)d_in[5];
    const float* b1   = (const float*)d_in[6];
    const float* W2   = (const float*)d_in[7];
    const float* b2   = (const float*)d_in[8];
    const float* W3   = (const float*)d_in[9];
    const float* b3   = (const float*)d_in[10];
    float* out = (float*)d_out;

    int B  = in_sizes[1];
    int HW = in_sizes[0] / (3 * B);
    int N  = B * HW;

    style_pre<<<B, HID>>>(sidx, emb, W0, b0);
    prep_w<<<512, 256>>>(W1, W2);

    cudaFuncSetAttribute(nilut_mma, cudaFuncAttributeMaxDynamicSharedMemorySize, SMEM_TOT);
    nilut_mma<<<N / MTILE, 256, SMEM_TOT>>>(rgb, W0, b1, b2, W3, b3, out, HW);
}

// round 8
// speedup vs baseline: 4.7696x; 1.0755x over previous
#include <cuda_runtime.h>
#include <cuda_fp16.h>
#include <cstdint>

#define HID 256
#define MTILE 64

// ---- smem byte offsets ----
#define OFF_A   0                 // 64 rows * 528 B (fp16 activations)
#define AROWB   528
#define OFF_WB  33792             // 2 buffers * 36864
#define WBUFSZ  36864             // 256 rows * 144 B (k=64 fp16 + 16B pad)
#define WROWB   144
#define OFF_RED 33792             // overlays WB after last GEMM: 64*3*4 floats
#define OFF_OVL 70656             // overlays WB buf1 during prologue
#define OVL_W0  0                 // 768 f32
#define OVL_CV  3072              // 256 f32
#define OVL_RGB 4096              // 192 f32
#define OFF_B1  107520
#define OFF_B2  108544
#define OFF_W3  109568            // [3][256] f32
#define OFF_B3  112640
#define SMEM_TOT 112656

// fp16 weights, transposed: [layer2][chunk4][n256][k64]
__device__ __align__(16) __half g_wb[131072];
__device__ float g_cstyle[16 * HID];

// ---------- helpers ----------
__device__ __forceinline__ uint32_t s2u(const void* p) {
    uint32_t a;
    asm("{ .reg .u64 t; cvta.to.shared.u64 t, %1; cvt.u32.u64 %0, t; }" : "=r"(a) : "l"(p));
    return a;
}
__device__ __forceinline__ void ldsm4(uint32_t* r, uint32_t addr) {
    asm volatile("ldmatrix.sync.aligned.m8n8.x4.shared.b16 {%0,%1,%2,%3}, [%4];"
                 : "=r"(r[0]), "=r"(r[1]), "=r"(r[2]), "=r"(r[3]) : "r"(addr));
}
__device__ __forceinline__ void mma16816(float* d, const uint32_t* a, uint32_t b0, uint32_t b1) {
    asm volatile("mma.sync.aligned.m16n8k16.row.col.f32.f16.f16.f32 "
                 "{%0,%1,%2,%3}, {%4,%5,%6,%7}, {%8,%9}, {%0,%1,%2,%3};"
                 : "+f"(d[0]), "+f"(d[1]), "+f"(d[2]), "+f"(d[3])
                 : "r"(a[0]), "r"(a[1]), "r"(a[2]), "r"(a[3]), "r"(b0), "r"(b1));
}
__device__ __forceinline__ void cpasync16(uint32_t dst, const void* src) {
    asm volatile("cp.async.cg.shared.global [%0], [%1], 16;" :: "r"(dst), "l"(src));
}
#define CP_COMMIT() asm volatile("cp.async.commit_group;" ::: "memory")
#define CP_WAIT(n)  asm volatile("cp.async.wait_group %0;" :: "n"(n) : "memory")

__device__ __forceinline__ float gelu_f(float x) {
    return 0.5f * x * (1.0f + erff(x * 0.70710678118654752f));
}
__device__ __forceinline__ uint32_t pack_h2(float lo, float hi) {
    __half2 h = __floats2half2_rn(lo, hi);
    return *(uint32_t*)&h;
}

// ---------- pre-kernels ----------
__global__ void style_pre(const int* __restrict__ sidx, const float* __restrict__ emb,
                          const float* __restrict__ W0, const float* __restrict__ b0) {
    int b = blockIdx.x, j = threadIdx.x;
    int s = sidx[b];
    float acc = b0[j];
#pragma unroll 8
    for (int k = 0; k < 64; k++)
        acc = fmaf(emb[s * 64 + k], W0[(3 + k) * HID + j], acc);
    g_cstyle[b * HID + j] = acc;
}

__global__ void prep_w(const float* __restrict__ W1, const float* __restrict__ W2) {
    int idx = blockIdx.x * 256 + threadIdx.x;     // 0..131071
    int l = idx >> 16;
    int k = (idx >> 8) & 255;
    int n = idx & 255;
    float w = (l ? W2 : W1)[k * HID + n];         // W[k][n] -> B[n][k]
    int chunk = k >> 6, kc = k & 63;
    g_wb[((size_t)(l * 4 + chunk) * 256 + n) * 64 + kc] = __float2half_rn(w);
}

// ---------- main kernel ----------
__device__ __forceinline__ void prefetch_chunk(uint32_t wb, const __half* gbase, int tid) {
    const char* g = (const char*)gbase + tid * 128;   // row tid, 128B
    uint32_t d = wb + tid * WROWB;
#pragma unroll
    for (int c = 0; c < 8; c++)
        cpasync16(d + c * 16, g + c * 16);
}

struct WarpCtx {
    int mg, ng, M0, lane;
    int arow, ak16off;
    int brow, bk16off;
};

__device__ __forceinline__ void run_layer(char* sm, uint32_t sb, const __half* gbase,
                                          const __half* tail, const WarpCtx& W,
                                          float C[2][8][4], int tid) {
    for (int c = 0; c < 4; c++) {
        __syncthreads();
        const __half* gn = (c < 3) ? gbase + (size_t)(c + 1) * 16384 : tail;
        if (gn) {
            prefetch_chunk(sb + OFF_WB + ((c + 1) & 1) * WBUFSZ, gn, tid);
            CP_COMMIT();
            CP_WAIT(1);
        } else {
            CP_WAIT(0);
        }
        __syncthreads();
        const uint32_t wb = sb + OFF_WB + (c & 1) * WBUFSZ;
#pragma unroll
        for (int kk = 0; kk < 64; kk += 16) {
            const int kglob = c * 64 + kk;
            uint32_t ah[2][4];
#pragma unroll
            for (int mt = 0; mt < 2; mt++) {
                uint32_t ao = sb + OFF_A + (uint32_t)(W.M0 + mt * 16 + W.arow) * AROWB
                              + (uint32_t)kglob * 2 + W.ak16off;
                ldsm4(ah[mt], ao);
            }
#pragma unroll
            for (int ntp = 0; ntp < 4; ntp++) {
                uint32_t bo = wb + (uint32_t)(W.ng * 64 + ntp * 16 + W.brow) * WROWB
                              + (uint32_t)kk * 2 + W.bk16off;
                uint32_t bh[4];
                ldsm4(bh, bo);
#pragma unroll
                for (int mt = 0; mt < 2; mt++) {
                    mma16816(C[mt][2 * ntp],     ah[mt], bh[0], bh[1]);
                    mma16816(C[mt][2 * ntp + 1], ah[mt], bh[2], bh[3]);
                }
            }
        }
    }
    __syncthreads();   // all LDSM reads done before A / RED gets rewritten
}

__global__ void __launch_bounds__(256, 2) nilut_mma(
    const float* __restrict__ rgb, const float* __restrict__ W0,
    const float* __restrict__ b1, const float* __restrict__ b2,
    const float* __restrict__ W3, const float* __restrict__ b3,
    float* __restrict__ out, int HW)
{
    extern __shared__ __align__(1024) char sm[];
    const uint32_t sb = s2u(sm);
    const int tid = threadIdx.x, wid = tid >> 5, lane = tid & 31;

    WarpCtx W;
    W.lane = lane;
    W.mg = wid & 1; W.ng = wid >> 1; W.M0 = W.mg * 32;
    W.arow = lane & 15;              W.ak16off = ((lane >> 4) & 1) * 16;
    W.brow = (lane & 7) + ((lane >> 4) << 3);
    W.bk16off = ((lane >> 3) & 1) * 16;

    const int pix0 = blockIdx.x * MTILE;
    const int b = pix0 / HW, hw0 = pix0 - b * HW;

    // start weight chunk (layer1, chunk0) prefetch ASAP -> buf0
    prefetch_chunk(sb + OFF_WB, g_wb, tid);
    CP_COMMIT();

    // stage resident + overlay smalls
    float* b1s = (float*)(sm + OFF_B1);
    float* b2s = (float*)(sm + OFF_B2);
    float* w3s = (float*)(sm + OFF_W3);
    float* b3s = (float*)(sm + OFF_B3);
    float* w0s  = (float*)(sm + OFF_OVL + OVL_W0);
    float* cvec = (float*)(sm + OFF_OVL + OVL_CV);
    float* rgbs = (float*)(sm + OFF_OVL + OVL_RGB);

    b1s[tid] = b1[tid];
    b2s[tid] = b2[tid];
#pragma unroll
    for (int c = 0; c < 3; c++) w3s[c * 256 + tid] = W3[3 * tid + c];
    if (tid < 4) b3s[tid] = (tid < 3) ? b3[tid] : 0.f;
    for (int i = tid; i < 768; i += 256) w0s[i] = W0[i];
    cvec[tid] = g_cstyle[b * HID + tid];
    if (tid < 192) {
        int c = tid >> 6, px = tid & 63;
        rgbs[c * 64 + px] = rgb[(size_t)(b * 3 + c) * HW + hw0 + px];
    }
    __syncthreads();

    // ---- layer 0 prologue: A = fp16(gelu(rgb.W0[0:3] + cvec)) ----
    {
        int pq = wid & 1, quarter = wid >> 1;   // 2 pixel groups x 4 j-quarters
        int p = pq * 32 + lane;                 // 0..63
        float rr = rgbs[p], gg = rgbs[64 + p], uu = rgbs[128 + p];
        char* arow = sm + OFF_A + p * AROWB;
#pragma unroll 4
        for (int q = 0; q < 32; q++) {
            int j = quarter * 64 + 2 * q;
            float2 w0a = *(const float2*)&w0s[j];
            float2 w0b = *(const float2*)&w0s[256 + j];
            float2 w0c = *(const float2*)&w0s[512 + j];
            float2 cv  = *(const float2*)&cvec[j];
            float a0 = fmaf(rr, w0a.x, fmaf(gg, w0b.x, fmaf(uu, w0c.x, cv.x)));
            float a1 = fmaf(rr, w0a.y, fmaf(gg, w0b.y, fmaf(uu, w0c.y, cv.y)));
            *(uint32_t*)(arow + j * 2) = pack_h2(gelu_f(a0), gelu_f(a1));
        }
    }

    float C[2][8][4];
#pragma unroll
    for (int mt = 0; mt < 2; mt++)
#pragma unroll
        for (int nt = 0; nt < 8; nt++)
#pragma unroll
            for (int q = 0; q < 4; q++) C[mt][nt][q] = 0.f;

    // ---- layer 1 GEMM ----
    run_layer(sm, sb, g_wb, g_wb + (size_t)4 * 16384, W, C, tid);

    // ---- epilogue 1: C -> gelu -> A (fp16), zero C ----
    {
        const int r0b = W.M0 + (lane >> 2);
#pragma unroll
        for (int mt = 0; mt < 2; mt++) {
            int r0 = r0b + mt * 16, r1 = r0 + 8;
#pragma unroll
            for (int nt = 0; nt < 8; nt++) {
                int j0 = W.ng * 64 + nt * 8 + (lane & 3) * 2;
                float2 bj = *(const float2*)(sm + OFF_B1 + j0 * 4);
                float v0 = gelu_f(C[mt][nt][0] + bj.x);
                float v1 = gelu_f(C[mt][nt][1] + bj.y);
                float v2 = gelu_f(C[mt][nt][2] + bj.x);
                float v3 = gelu_f(C[mt][nt][3] + bj.y);
                *(uint32_t*)(sm + OFF_A + r0 * AROWB + j0 * 2) = pack_h2(v0, v1);
                *(uint32_t*)(sm + OFF_A + r1 * AROWB + j0 * 2) = pack_h2(v2, v3);
                C[mt][nt][0] = 0.f; C[mt][nt][1] = 0.f;
                C[mt][nt][2] = 0.f; C[mt][nt][3] = 0.f;
            }
        }
    }
    __syncthreads();   // A ready for layer 2

    // ---- layer 2 GEMM (chunk0 already prefetched by layer-1 tail) ----
    run_layer(sm, sb, g_wb + (size_t)4 * 16384, nullptr, W, C, tid);

    // ---- head epilogue: gelu -> dot W3 -> reduce -> sigmoid ----
    {
        float* red = (float*)(sm + OFF_RED);   // [64][3][4]
        float acc[2][2][3];
#pragma unroll
        for (int mt = 0; mt < 2; mt++)
#pragma unroll
            for (int h = 0; h < 2; h++)
                acc[mt][h][0] = acc[mt][h][1] = acc[mt][h][2] = 0.f;

#pragma unroll
        for (int mt = 0; mt < 2; mt++) {
#pragma unroll
            for (int nt = 0; nt < 8; nt++) {
                int j0 = W.ng * 64 + nt * 8 + (lane & 3) * 2;
                float2 bj = *(const float2*)(sm + OFF_B2 + j0 * 4);
                float2 wx = *(const float2*)(sm + OFF_W3 + j0 * 4);
                float2 wy = *(const float2*)(sm + OFF_W3 + 1024 + j0 * 4);
                float2 wz = *(const float2*)(sm + OFF_W3 + 2048 + j0 * 4);
                float v0 = gelu_f(C[mt][nt][0] + bj.x);
                float v1 = gelu_f(C[mt][nt][1] + bj.y);
                float v2 = gelu_f(C[mt][nt][2] + bj.x);
                float v3 = gelu_f(C[mt][nt][3] + bj.y);
                acc[mt][0][0] = fmaf(v0, wx.x, fmaf(v1, wx.y, acc[mt][0][0]));
                acc[mt][0][1] = fmaf(v0, wy.x, fmaf(v1, wy.y, acc[mt][0][1]));
                acc[mt][0][2] = fmaf(v0, wz.x, fmaf(v1, wz.y, acc[mt][0][2]));
                acc[mt][1][0] = fmaf(v2, wx.x, fmaf(v3, wx.y, acc[mt][1][0]));
                acc[mt][1][1] = fmaf(v2, wy.x, fmaf(v3, wy.y, acc[mt][1][1]));
                acc[mt][1][2] = fmaf(v2, wz.x, fmaf(v3, wz.y, acc[mt][1][2]));
            }
        }
#pragma unroll
        for (int mt = 0; mt < 2; mt++)
#pragma unroll
            for (int h = 0; h < 2; h++)
#pragma unroll
                for (int ch = 0; ch < 3; ch++) {
                    float v = acc[mt][h][ch];
                    v += __shfl_xor_sync(0xffffffffu, v, 1);
                    v += __shfl_xor_sync(0xffffffffu, v, 2);
                    acc[mt][h][ch] = v;
                }
        if ((lane & 3) == 0) {
#pragma unroll
            for (int mt = 0; mt < 2; mt++)
#pragma unroll
                for (int h = 0; h < 2; h++) {
                    int r = W.M0 + mt * 16 + (lane >> 2) + h * 8;
#pragma unroll
                    for (int ch = 0; ch < 3; ch++)
                        red[(r * 3 + ch) * 4 + W.ng] = acc[mt][h][ch];
                }
        }
        __syncthreads();
        if (tid < 192) {
            int ch = tid >> 6, row = tid & 63;
            const float* rr = &red[(row * 3 + ch) * 4];
            float s = rr[0] + rr[1] + rr[2] + rr[3] + b3s[ch];
            out[(size_t)(b * 3 + ch) * HW + hw0 + row] = 1.f / (1.f + expf(-s));
        }
    }
}

extern "C" void kernel_launch(void* const* d_in, const int* in_sizes, int n_in,
                              void* d_out, int out_size) {
    const float* rgb  = (const float*)d_in[0];
    const int*   sidx = (const int*)  d_in[1];
    const float* emb  = (const float*)d_in[2];
    const float* W0   = (const float*)d_in[3];
    const float* b0   = (const float*)d_in[4];
    const float* W1   = (const float*)d_in[5];
    const float* b1   = (const float*)d_in[6];
    const float* W2   = (const float*)d_in[7];
    const float* b2   = (const float*)d_in[8];
    const float* W3   = (const float*)d_in[9];
    const float* b3   = (const float*)d_in[10];
    float* out = (float*)d_out;

    int B  = in_sizes[1];
    int HW = in_sizes[0] / (3 * B);
    int N  = B * HW;

    style_pre<<<B, HID>>>(sidx, emb, W0, b0);
    prep_w<<<512, 256>>>(W1, W2);

    cudaFuncSetAttribute(nilut_mma, cudaFuncAttributeMaxDynamicSharedMemorySize, SMEM_TOT);
    nilut_mma<<<N / MTILE, 256, SMEM_TOT>>>(rgb, W0, b1, b2, W3, b3, out, HW);
}